// round 15
// baseline (speedup 1.0000x reference)
#include <cuda_runtime.h>
#include <cuda_bf16.h>
#include <cstdint>

#define BATCH 2048
#define INF   512
#define OUTF  512
#define NAG   64

#define MT   128            /* block M, 4 warps x 32 */
#define NT   32             /* N rows per (agent, z) pass */
#define TK   32             /* k chunk */
#define NCH  (INF / TK)     /* 16 */

/* smem: W single stage (hi 10240 + lo 10240) + per-warp X (2 stages) */
#define WROW_B   80
#define W_HI     0
#define W_LO     10240
#define XBASE    20480
#define XSTG     5120            /* per stage per warp: hi 2560 + lo 2560 */
#define XLO_OFF  2560
#define XWARP    (2 * XSTG)      /* 10240 per warp */
#define SM_TOT   (XBASE + 4 * XWARP)   /* 61440 */

__device__ int g_bucket[BATCH];
__device__ int g_offsets[NAG + 1];
/* X pre-converted, BUCKET-ordered, transposed: [chunk][q(0-3 hi,4-7 lo)][slot] 16B */
__device__ uint4 g_xs2[NCH * 8 * BATCH];

__device__ __forceinline__ uint32_t smem_u32(const void* p) {
    uint32_t a;
    asm("{ .reg .u64 t; cvta.to.shared.u64 t, %1; cvt.u32.u64 %0, t; }" : "=r"(a) : "l"(p));
    return a;
}

#define LDSM_X4(r0, r1, r2, r3, addr) \
    asm volatile("ldmatrix.sync.aligned.m8n8.x4.shared.b16 {%0,%1,%2,%3}, [%4];" \
        : "=r"(r0), "=r"(r1), "=r"(r2), "=r"(r3) : "r"(addr))

#define CP_ASYNC16(dst, src) \
    asm volatile("cp.async.cg.shared.global [%0], [%1], 16;" :: "r"(dst), "l"(src) : "memory")
#define CP_COMMIT()    asm volatile("cp.async.commit_group;" ::: "memory")
#define CP_WAIT_G1()   asm volatile("cp.async.wait_group 1;" ::: "memory")
#define CP_WAIT_G0()   asm volatile("cp.async.wait_group 0;" ::: "memory")

/* split 2 floats into packed bf16 hi-word and residual lo-word (lo 16 bits = f0) */
__device__ __forceinline__ void split2(float f0, float f1, uint32_t& h, uint32_t& l) {
    asm("cvt.rn.bf16x2.f32 %0, %1, %2;" : "=r"(h) : "f"(f1), "f"(f0));
    float r0 = f0 - __uint_as_float(h << 16);
    float r1 = f1 - __uint_as_float(h & 0xFFFF0000u);
    asm("cvt.rn.bf16x2.f32 %0, %1, %2;" : "=r"(l) : "f"(r1), "f"(r0));
}

__device__ __forceinline__ void mma_bf16(float* c, const uint32_t* a, const uint32_t* b) {
    asm volatile(
        "mma.sync.aligned.m16n8k16.row.col.f32.bf16.bf16.f32 "
        "{%0,%1,%2,%3}, {%4,%5,%6,%7}, {%8,%9}, {%0,%1,%2,%3};"
        : "+f"(c[0]), "+f"(c[1]), "+f"(c[2]), "+f"(c[3])
        : "r"(a[0]), "r"(a[1]), "r"(a[2]), "r"(a[3]), "r"(b[0]), "r"(b[1]));
}

/* ---------------- kernel 1: counting sort by agent ---------------- */
__global__ __launch_bounds__(1024) void bucket_kernel(const int* __restrict__ which) {
    __shared__ int cnt[NAG];
    __shared__ int run[NAG];
    const int t = threadIdx.x;
    if (t < NAG) cnt[t] = 0;
    __syncthreads();
    for (int i = t; i < BATCH; i += blockDim.x) atomicAdd(&cnt[which[i]], 1);
    __syncthreads();
    if (t == 0) {
        int s = 0;
        for (int a = 0; a < NAG; a++) { run[a] = s; g_offsets[a] = s; s += cnt[a]; }
        g_offsets[NAG] = s;
    }
    __syncthreads();
    for (int i = t; i < BATCH; i += blockDim.x) {
        const int a = which[i];
        g_bucket[atomicAdd(&run[a], 1)] = i;
    }
}

/* ------- kernel 2: convert X to bucket-ordered transposed bf16 hi/lo -------
   8 slots per block (warp per slot). lane: chunk c = l>>1, k-half h = l&1.   */
__global__ __launch_bounds__(256) void convert_kernel(const float* __restrict__ x) {
    const int t = threadIdx.x;
    const int slot = blockIdx.x * 8 + (t >> 5);
    const int l = t & 31;
    const int c = l >> 1, h = l & 1;
    const int row = g_bucket[slot];
    const float4* src = (const float4*)(x + (size_t)row * INF + c * TK + h * 16);
    uint32_t hi[8], lo[8];
    #pragma unroll
    for (int p = 0; p < 4; p++) {
        const float4 v = src[p];
        split2(v.x, v.y, hi[2 * p],     lo[2 * p]);
        split2(v.z, v.w, hi[2 * p + 1], lo[2 * p + 1]);
    }
    uint4* base = g_xs2 + (size_t)(c * 8) * BATCH;
    base[(size_t)(h * 2 + 0) * BATCH + slot] = make_uint4(hi[0], hi[1], hi[2], hi[3]);
    base[(size_t)(h * 2 + 1) * BATCH + slot] = make_uint4(hi[4], hi[5], hi[6], hi[7]);
    base[(size_t)(4 + h * 2) * BATCH + slot] = make_uint4(lo[0], lo[1], lo[2], lo[3]);
    base[(size_t)(5 + h * 2) * BATCH + slot] = make_uint4(lo[4], lo[5], lo[6], lo[7]);
}

/* ---------------- kernel 3: warp-decoupled split-bf16 mma GEMM ----------------
   NO __syncthreads anywhere: W smem rows and X smem copies are per-warp
   exclusive; all ordering is __syncwarp + cp.async groups.
*/
__global__ __launch_bounds__(128, 3) void agent_mma_kernel(
    const float* __restrict__ x, const float* __restrict__ w,
    const float* __restrict__ bias, float* __restrict__ out)
{
    extern __shared__ char sm[];
    const uint32_t sb = smem_u32(sm);
    const int a     = blockIdx.y;
    const int mbase = blockIdx.x * MT;
    const int off   = g_offsets[a];
    const int cnt   = g_offsets[a + 1] - off;

    const int t    = threadIdx.x;
    const int lane = t & 31;
    const int warp = t >> 5;
    const int qr   = lane >> 2;
    const int qc   = lane & 3;

    const uint32_t xwbase = sb + XBASE + (uint32_t)warp * XWARP;

    /* ldmatrix per-lane address bases */
    const int aRow = ((lane >> 3) & 1) * 8;
    const int aK16 = ((lane >> 4) & 1) * 16;
    const int bRow = ((lane >> 4) & 1) * 8;
    const int bK16 = ((lane >> 3) & 1) * 16;
    uint32_t awb[2], bxb[2];
    #pragma unroll
    for (int mi = 0; mi < 2; mi++)
        awb[mi] = sb + W_HI
                + (uint32_t)(warp * 32 + mi * 16 + aRow + (lane & 7)) * WROW_B + aK16;
    #pragma unroll
    for (int nb = 0; nb < 2; nb++)
        bxb[nb] = xwbase + (uint32_t)(nb * 16 + bRow + (lane & 7)) * WROW_B + bK16;

    /* coalesced W load mapping */
    const int wlr = lane >> 3;
    const int wlc = lane & 7;
    const float* Wbase = w + (size_t)a * OUTF * INF
                       + (size_t)(mbase + warp * 32 + wlr) * INF + wlc * 4;
    const uint32_t wsoff = (uint32_t)(warp * 32 + wlr) * WROW_B + wlc * 8;

    /* X cp mapping: lane <-> n-row */
    const uint32_t xdst = xwbase + (uint32_t)lane * WROW_B;

    float4 wpre[2][8];

    for (int n0 = blockIdx.z * NT; n0 < cnt; n0 += 2 * NT) {
        const int cntc = min(NT, cnt - n0);
        int sg = off + n0 + lane;
        if (sg > BATCH - 1) sg = BATCH - 1;
        const char* xsrc0 = (const char*)(g_xs2) + (size_t)sg * 16;

        float acc[2][4][4];
        #pragma unroll
        for (int mi = 0; mi < 2; mi++)
            #pragma unroll
            for (int ni = 0; ni < 4; ni++)
                #pragma unroll
                for (int r = 0; r < 4; r++) acc[mi][ni][r] = 0.f;

        auto ldg_w = [&](int c) {
            const int k0 = c * TK;
            float4* dst = wpre[c & 1];
            #pragma unroll
            for (int ro = 0; ro < 8; ro++)
                dst[ro] = *(const float4*)(Wbase + (size_t)ro * 4 * INF + k0);
        };
        auto cp_x = [&](int c) {
            const uint32_t so = (uint32_t)(c & 1) * XSTG;
            const char* src = xsrc0 + (size_t)(c * 8) * BATCH * 16;
            #pragma unroll
            for (int q = 0; q < 4; q++) {
                CP_ASYNC16(xdst + so + q * 16,           src + (size_t)q * BATCH * 16);
                CP_ASYNC16(xdst + so + XLO_OFF + q * 16, src + (size_t)(4 + q) * BATCH * 16);
            }
            CP_COMMIT();
        };
        auto sts_w = [&](int c) {
            char* dw = sm + wsoff;
            const float4* src = wpre[c & 1];
            #pragma unroll
            for (int ro = 0; ro < 8; ro++) {
                uint32_t h0, l0, h1, l1;
                split2(src[ro].x, src[ro].y, h0, l0);
                split2(src[ro].z, src[ro].w, h1, l1);
                const uint32_t roff = (uint32_t)ro * 4 * WROW_B;
                *(uint2*)(dw + W_HI + roff) = make_uint2(h0, h1);
                *(uint2*)(dw + W_LO + roff) = make_uint2(l0, l1);
            }
        };

        auto compute = [&](int s) {   /* s = X stage index; W is single-stage */
            const uint32_t sx = (uint32_t)s * XSTG;
            #pragma unroll
            for (int kk = 0; kk < 2; kk++) {
                const uint32_t koA = kk * 32;
                const uint32_t koB = sx + kk * 32;
                uint32_t ahi[2][4], alo[2][4];
                #pragma unroll
                for (int mi = 0; mi < 2; mi++) {
                    LDSM_X4(ahi[mi][0], ahi[mi][1], ahi[mi][2], ahi[mi][3], awb[mi] + koA);
                    LDSM_X4(alo[mi][0], alo[mi][1], alo[mi][2], alo[mi][3], awb[mi] + (W_LO - W_HI) + koA);
                }
                #pragma unroll
                for (int nb = 0; nb < 2; nb++) {
                    uint32_t bh4[4], bl4[4];
                    LDSM_X4(bh4[0], bh4[1], bh4[2], bh4[3], bxb[nb] + koB);
                    LDSM_X4(bl4[0], bl4[1], bl4[2], bl4[3], bxb[nb] + XLO_OFF + koB);
                    #pragma unroll
                    for (int half = 0; half < 2; half++) {
                        const int ni = nb * 2 + half;
                        uint32_t bh[2] = {bh4[2 * half], bh4[2 * half + 1]};
                        uint32_t bl[2] = {bl4[2 * half], bl4[2 * half + 1]};
                        #pragma unroll
                        for (int mi = 0; mi < 2; mi++) {
                            mma_bf16(acc[mi][ni], ahi[mi], bh);
                            mma_bf16(acc[mi][ni], alo[mi], bh);
                            mma_bf16(acc[mi][ni], ahi[mi], bl);
                        }
                    }
                }
            }
        };

        /* prologue (warp-local) */
        ldg_w(0);
        ldg_w(1);
        cp_x(0);
        cp_x(1);
        sts_w(0);
        CP_WAIT_G1();        /* X(0) landed */
        __syncwarp();

        for (int c = 0; c < NCH; c++) {
            compute(c & 1);
            if (c + 2 < NCH) { cp_x(c + 2); ldg_w(c + 2); }
            __syncwarp();
            if (c + 1 < NCH) sts_w(c + 1);
            if (c + 2 < NCH) CP_WAIT_G1();
            else             CP_WAIT_G0();
            __syncwarp();
        }

        /* epilogue (no block sync needed: all state is warp-private) */
        #pragma unroll
        for (int mi = 0; mi < 2; mi++) {
            const int mg = mbase + warp * 32 + mi * 16 + qr;
            const float b0 = bias[a * OUTF + mg];
            const float b8 = bias[a * OUTF + mg + 8];
            #pragma unroll
            for (int ni = 0; ni < 4; ni++) {
                const int n = ni * 8 + qc * 2;
                if (n < cntc) {
                    const int r = g_bucket[off + n0 + n];
                    out[(size_t)r * OUTF + mg]     = acc[mi][ni][0] + b0;
                    out[(size_t)r * OUTF + mg + 8] = acc[mi][ni][2] + b8;
                }
                if (n + 1 < cntc) {
                    const int r = g_bucket[off + n0 + n + 1];
                    out[(size_t)r * OUTF + mg]     = acc[mi][ni][1] + b0;
                    out[(size_t)r * OUTF + mg + 8] = acc[mi][ni][3] + b8;
                }
            }
        }
    }
}

extern "C" void kernel_launch(void* const* d_in, const int* in_sizes, int n_in,
                              void* d_out, int out_size) {
    const int*   which = (const int*)d_in[0];
    const float* x     = (const float*)d_in[1];
    const float* w     = (const float*)d_in[2];
    const float* b     = (const float*)d_in[3];
    float* out = (float*)d_out;

    cudaFuncSetAttribute(agent_mma_kernel,
                         cudaFuncAttributeMaxDynamicSharedMemorySize, SM_TOT);

    bucket_kernel<<<1, 1024>>>(which);
    convert_kernel<<<BATCH / 8, 256>>>(x);
    agent_mma_kernel<<<dim3(OUTF / MT, NAG, 2), 128, SM_TOT>>>(x, w, b, out);
}

// round 16
// speedup vs baseline: 1.4237x; 1.4237x over previous
#include <cuda_runtime.h>
#include <cuda_bf16.h>
#include <cstdint>

#define BATCH 2048
#define INF   512
#define OUTF  512
#define NAG   64

#define MT   128            /* block M (out features), 4 warps x 32 */
#define NT   32             /* block N (batch rows) */
#define TK   32             /* k chunk */
#define NCH  (INF / TK)     /* 16 */

/* smem per stage: Whi[128x32 bf16, row stride 80B] + Wlo + Xhi[32x32] + Xlo */
#define WROW_B   80
#define ST_WHI   0
#define ST_WLO   10240
#define ST_XHI   20480
#define ST_XLO   23040
#define ST_SIZE  25600
#define SM_TOT   (2 * ST_SIZE)   /* 51200 bytes */

__device__ int g_bucket[BATCH];
__device__ int g_offsets[NAG + 1];
/* X pre-converted: per (chunk, row): 32 u32 = [q: 4 hi, 4 lo] x4, 128B */
__device__ uint32_t g_xs[NCH][BATCH][32];

__device__ __forceinline__ uint32_t smem_u32(const void* p) {
    uint32_t a;
    asm("{ .reg .u64 t; cvta.to.shared.u64 t, %1; cvt.u32.u64 %0, t; }" : "=r"(a) : "l"(p));
    return a;
}

#define LDSM_X4(r0, r1, r2, r3, addr) \
    asm volatile("ldmatrix.sync.aligned.m8n8.x4.shared.b16 {%0,%1,%2,%3}, [%4];" \
        : "=r"(r0), "=r"(r1), "=r"(r2), "=r"(r3) : "r"(addr))

#define CP_ASYNC16(dst, src) \
    asm volatile("cp.async.cg.shared.global [%0], [%1], 16;" :: "r"(dst), "l"(src) : "memory")
#define CP_COMMIT()    asm volatile("cp.async.commit_group;" ::: "memory")
#define CP_WAIT_G0()   asm volatile("cp.async.wait_group 0;" ::: "memory")

/* split 2 floats into packed bf16 hi-word and residual lo-word (lo 16 bits = f0) */
__device__ __forceinline__ void split2(float f0, float f1, uint32_t& h, uint32_t& l) {
    asm("cvt.rn.bf16x2.f32 %0, %1, %2;" : "=r"(h) : "f"(f1), "f"(f0));
    float r0 = f0 - __uint_as_float(h << 16);
    float r1 = f1 - __uint_as_float(h & 0xFFFF0000u);
    asm("cvt.rn.bf16x2.f32 %0, %1, %2;" : "=r"(l) : "f"(r1), "f"(r0));
}

__device__ __forceinline__ void mma_bf16(float* c, const uint32_t* a, const uint32_t* b) {
    asm volatile(
        "mma.sync.aligned.m16n8k16.row.col.f32.bf16.bf16.f32 "
        "{%0,%1,%2,%3}, {%4,%5,%6,%7}, {%8,%9}, {%0,%1,%2,%3};"
        : "+f"(c[0]), "+f"(c[1]), "+f"(c[2]), "+f"(c[3])
        : "r"(a[0]), "r"(a[1]), "r"(a[2]), "r"(a[3]), "r"(b[0]), "r"(b[1]));
}

/* ------- kernel 1: block 0 = counting sort; blocks 1.. = X convert ------- */
__global__ __launch_bounds__(256) void prep_kernel(
    const int* __restrict__ which, const float* __restrict__ x)
{
    const int t = threadIdx.x;
    if (blockIdx.x == 0) {
        __shared__ int cnt[NAG];
        __shared__ int run[NAG];
        if (t < NAG) cnt[t] = 0;
        __syncthreads();
        for (int i = t; i < BATCH; i += 256) atomicAdd(&cnt[which[i]], 1);
        __syncthreads();
        if (t == 0) {
            int s = 0;
            for (int a = 0; a < NAG; a++) { run[a] = s; g_offsets[a] = s; s += cnt[a]; }
            g_offsets[NAG] = s;
        }
        __syncthreads();
        for (int i = t; i < BATCH; i += 256) {
            const int a = which[i];
            g_bucket[atomicAdd(&run[a], 1)] = i;
        }
        return;
    }
    /* convert: 16 rows per block (8 warps x 2 rows, half-warp per row) */
    const int warp = t >> 5, lane = t & 31;
    const int row = (blockIdx.x - 1) * 16 + warp * 2 + (lane >> 4);
    if (row >= BATCH) return;
    const int p = lane & 15;                 /* k-pair within chunk */
    const float2* xr = (const float2*)(x + (size_t)row * INF) + p;
    const int q = p >> 2, w = p & 3;
    #pragma unroll
    for (int c = 0; c < NCH; c++) {
        const float2 v = xr[c * 16];
        uint32_t h, l;
        split2(v.x, v.y, h, l);
        uint32_t* dst = g_xs[c][row];
        dst[q * 8 + w]     = h;
        dst[q * 8 + 4 + w] = l;
    }
}

/* ---------------- kernel 2: split-bf16 mma.sync GEMM ----------------
   R10 structure, reordered loop: sts_w(c+1) consumes W regs loaded one
   full iteration earlier (ldg lookahead 2), hiding W LDG latency at the
   SAME one-barrier-per-chunk cost.
*/
__global__ __launch_bounds__(128, 3) void agent_mma_kernel(
    const float* __restrict__ x, const float* __restrict__ w,
    const float* __restrict__ bias, float* __restrict__ out)
{
    extern __shared__ char sm[];
    const uint32_t sb = smem_u32(sm);
    const int a     = blockIdx.y;
    const int mbase = blockIdx.x * MT;
    const int off   = g_offsets[a];
    const int cnt   = g_offsets[a + 1] - off;

    const int t    = threadIdx.x;
    const int lane = t & 31;
    const int warp = t >> 5;
    const int qr   = lane >> 2;
    const int qc   = lane & 3;

    /* ldmatrix per-lane address bases */
    const int aRow = ((lane >> 3) & 1) * 8;
    const int aK16 = ((lane >> 4) & 1) * 16;
    const int bRow = ((lane >> 4) & 1) * 8;
    const int bK16 = ((lane >> 3) & 1) * 16;
    uint32_t awb[2], alb[2], bxb[2], blb[2];
    #pragma unroll
    for (int mi = 0; mi < 2; mi++) {
        const uint32_t ro = (uint32_t)(warp * 32 + mi * 16 + aRow + (lane & 7)) * WROW_B + aK16;
        awb[mi] = sb + ST_WHI + ro;
        alb[mi] = sb + ST_WLO + ro;
    }
    #pragma unroll
    for (int nb = 0; nb < 2; nb++) {
        const uint32_t ro = (uint32_t)(nb * 16 + bRow + (lane & 7)) * WROW_B + bK16;
        bxb[nb] = sb + ST_XHI + ro;
        blb[nb] = sb + ST_XLO + ro;
    }

    /* coalesced W load mapping: 4 rows per warp-pass, 8 passes per chunk */
    const int wlr = lane >> 3;
    const int wlc = lane & 7;
    const float* Wbase = w + (size_t)a * OUTF * INF
                       + (size_t)(mbase + warp * 32 + wlr) * INF + wlc * 4;
    const uint32_t wsrow = (uint32_t)(warp * 32 + wlr);

    /* X mapping: slot = t>>2 (0..31), q = t&3 */
    const int xslot = t >> 2, xq4 = t & 3;
    const uint32_t xdst = sb + (uint32_t)xslot * WROW_B + xq4 * 16;

    float4 wpre[2][8];   /* two chunk buffers, index = chunk & 1 */

    for (int n0 = blockIdx.z * NT; n0 < cnt; n0 += 2 * NT) {
        const int cntc = min(NT, cnt - n0);
        int sg = off + n0 + xslot;
        if (sg > BATCH - 1) sg = BATCH - 1;
        const int xrowg = g_bucket[sg];

        float acc[2][4][4];
        #pragma unroll
        for (int mi = 0; mi < 2; mi++)
            #pragma unroll
            for (int ni = 0; ni < 4; ni++)
                #pragma unroll
                for (int r = 0; r < 4; r++) acc[mi][ni][r] = 0.f;

        auto ldg_w = [&](int c) {
            const int k0 = c * TK;
            float4* dst = wpre[c & 1];
            #pragma unroll
            for (int ro = 0; ro < 8; ro++)
                dst[ro] = *(const float4*)(Wbase + (size_t)ro * 4 * INF + k0);
        };
        auto cp_x = [&](int c) {
            const uint32_t so = (uint32_t)(c & 1) * ST_SIZE;
            const uint32_t* xsrc = &g_xs[c][xrowg][xq4 * 8];
            CP_ASYNC16(xdst + ST_XHI + so, xsrc);
            CP_ASYNC16(xdst + ST_XLO + so, xsrc + 4);
            CP_COMMIT();
        };
        auto sts_w = [&](int c) {
            char* dw = sm + (size_t)(c & 1) * ST_SIZE + wsrow * WROW_B + wlc * 8;
            const float4* src = wpre[c & 1];
            #pragma unroll
            for (int ro = 0; ro < 8; ro++) {
                uint32_t h0, l0, h1, l1;
                split2(src[ro].x, src[ro].y, h0, l0);
                split2(src[ro].z, src[ro].w, h1, l1);
                const uint32_t roff = (uint32_t)ro * 4 * WROW_B;
                *(uint2*)(dw + ST_WHI + roff) = make_uint2(h0, h1);
                *(uint2*)(dw + ST_WLO + roff) = make_uint2(l0, l1);
            }
        };

        auto compute = [&](int s) {        /* s = stage index (0/1) */
            const uint32_t so = (uint32_t)s * ST_SIZE;
            #pragma unroll
            for (int kk = 0; kk < 2; kk++) {
                const uint32_t ko = so + kk * 32;
                uint32_t ahi[2][4], alo[2][4];
                #pragma unroll
                for (int mi = 0; mi < 2; mi++) {
                    LDSM_X4(ahi[mi][0], ahi[mi][1], ahi[mi][2], ahi[mi][3], awb[mi] + ko);
                    LDSM_X4(alo[mi][0], alo[mi][1], alo[mi][2], alo[mi][3], alb[mi] + ko);
                }
                #pragma unroll
                for (int nb = 0; nb < 2; nb++) {
                    uint32_t bh4[4], bl4[4];
                    LDSM_X4(bh4[0], bh4[1], bh4[2], bh4[3], bxb[nb] + ko);
                    LDSM_X4(bl4[0], bl4[1], bl4[2], bl4[3], blb[nb] + ko);
                    #pragma unroll
                    for (int half = 0; half < 2; half++) {
                        const int ni = nb * 2 + half;
                        uint32_t bh[2] = {bh4[2 * half], bh4[2 * half + 1]};
                        uint32_t bl[2] = {bl4[2 * half], bl4[2 * half + 1]};
                        #pragma unroll
                        for (int mi = 0; mi < 2; mi++) {
                            mma_bf16(acc[mi][ni], ahi[mi], bh);
                            mma_bf16(acc[mi][ni], alo[mi], bh);
                            mma_bf16(acc[mi][ni], ahi[mi], bl);
                        }
                    }
                }
            }
        };

        /* prologue: stage0 ready, wbuf[1] loaded, X(0) landed */
        ldg_w(0);
        sts_w(0);
        cp_x(0);
        ldg_w(1);
        CP_WAIT_G0();

        for (int c = 0; c < NCH; c++) {
            __syncthreads();                 /* publish stage c; free stage c+1 */
            if (c + 1 < NCH) {
                sts_w(c + 1);                /* W regs loaded one iter earlier */
                cp_x(c + 1);
            }
            if (c + 2 < NCH) ldg_w(c + 2);   /* into wbuf[c&1], freed by sts_w(c) */
            compute(c & 1);
            if (c + 1 < NCH) CP_WAIT_G0();   /* X(c+1) landed before next bar */
        }

        /* epilogue */
        #pragma unroll
        for (int mi = 0; mi < 2; mi++) {
            const int mg = mbase + warp * 32 + mi * 16 + qr;
            const float b0 = bias[a * OUTF + mg];
            const float b8 = bias[a * OUTF + mg + 8];
            #pragma unroll
            for (int ni = 0; ni < 4; ni++) {
                const int n = ni * 8 + qc * 2;
                if (n < cntc) {
                    const int r = g_bucket[off + n0 + n];
                    out[(size_t)r * OUTF + mg]     = acc[mi][ni][0] + b0;
                    out[(size_t)r * OUTF + mg + 8] = acc[mi][ni][2] + b8;
                }
                if (n + 1 < cntc) {
                    const int r = g_bucket[off + n0 + n + 1];
                    out[(size_t)r * OUTF + mg]     = acc[mi][ni][1] + b0;
                    out[(size_t)r * OUTF + mg + 8] = acc[mi][ni][3] + b8;
                }
            }
        }
        __syncthreads();
    }
}

extern "C" void kernel_launch(void* const* d_in, const int* in_sizes, int n_in,
                              void* d_out, int out_size) {
    const int*   which = (const int*)d_in[0];
    const float* x     = (const float*)d_in[1];
    const float* w     = (const float*)d_in[2];
    const float* b     = (const float*)d_in[3];
    float* out = (float*)d_out;

    cudaFuncSetAttribute(agent_mma_kernel,
                         cudaFuncAttributeMaxDynamicSharedMemorySize, SM_TOT);

    prep_kernel<<<1 + (BATCH + 15) / 16, 256>>>(which, x);
    agent_mma_kernel<<<dim3(OUTF / MT, NAG, 2), 128, SM_TOT>>>(x, w, b, out);
}

// round 17
// speedup vs baseline: 2.0926x; 1.4699x over previous
#include <cuda_runtime.h>
#include <cuda_bf16.h>
#include <cstdint>

#define BATCH 2048
#define INF   512
#define OUTF  512
#define NAG   64

#define MT   128            /* block M (out features), 4 warps x 32 */
#define NT   32             /* block N (batch rows) */
#define TK   32             /* k chunk */
#define NCH  (INF / TK)     /* 16 */
#define NCH2 (NCH / 2)      /* 8 chunks per k-half block */

/* smem per stage: Whi[128x32 bf16, row stride 80B] + Wlo + Xhi[32x32] + Xlo */
#define WROW_B   80
#define ST_WHI   0
#define ST_WLO   10240
#define ST_XHI   20480
#define ST_XLO   23040
#define ST_SIZE  25600
#define SM_TOT   (2 * ST_SIZE)   /* 51200 bytes */

__device__ int g_bucket[BATCH];
__device__ int g_offsets[NAG + 1];
/* X pre-converted: per (chunk, row): 32 u32 = [q: 4 hi, 4 lo] x4, 128B */
__device__ uint32_t g_xs[NCH][BATCH][32];

__device__ __forceinline__ uint32_t smem_u32(const void* p) {
    uint32_t a;
    asm("{ .reg .u64 t; cvta.to.shared.u64 t, %1; cvt.u32.u64 %0, t; }" : "=r"(a) : "l"(p));
    return a;
}

#define LDSM_X4(r0, r1, r2, r3, addr) \
    asm volatile("ldmatrix.sync.aligned.m8n8.x4.shared.b16 {%0,%1,%2,%3}, [%4];" \
        : "=r"(r0), "=r"(r1), "=r"(r2), "=r"(r3) : "r"(addr))

#define CP_ASYNC16(dst, src) \
    asm volatile("cp.async.cg.shared.global [%0], [%1], 16;" :: "r"(dst), "l"(src) : "memory")
#define CP_WAIT_ALL() asm volatile("cp.async.wait_all;" ::: "memory")

/* split 2 floats into packed bf16 hi-word and residual lo-word (lo 16 bits = f0) */
__device__ __forceinline__ void split2(float f0, float f1, uint32_t& h, uint32_t& l) {
    asm("cvt.rn.bf16x2.f32 %0, %1, %2;" : "=r"(h) : "f"(f1), "f"(f0));
    float r0 = f0 - __uint_as_float(h << 16);
    float r1 = f1 - __uint_as_float(h & 0xFFFF0000u);
    asm("cvt.rn.bf16x2.f32 %0, %1, %2;" : "=r"(l) : "f"(r1), "f"(r0));
}

__device__ __forceinline__ void mma_bf16(float* c, const uint32_t* a, const uint32_t* b) {
    asm volatile(
        "mma.sync.aligned.m16n8k16.row.col.f32.bf16.bf16.f32 "
        "{%0,%1,%2,%3}, {%4,%5,%6,%7}, {%8,%9}, {%0,%1,%2,%3};"
        : "+f"(c[0]), "+f"(c[1]), "+f"(c[2]), "+f"(c[3])
        : "r"(a[0]), "r"(a[1]), "r"(a[2]), "r"(a[3]), "r"(b[0]), "r"(b[1]));
}

/* ------- kernel 1: block 0 = counting sort; blocks 1.. = X convert ------- */
__global__ __launch_bounds__(256) void prep_kernel(
    const int* __restrict__ which, const float* __restrict__ x)
{
    const int t = threadIdx.x;
    if (blockIdx.x == 0) {
        __shared__ int cnt[NAG];
        __shared__ int run[NAG];
        if (t < NAG) cnt[t] = 0;
        __syncthreads();
        for (int i = t; i < BATCH; i += 256) atomicAdd(&cnt[which[i]], 1);
        __syncthreads();
        if (t == 0) {
            int s = 0;
            for (int a = 0; a < NAG; a++) { run[a] = s; g_offsets[a] = s; s += cnt[a]; }
            g_offsets[NAG] = s;
        }
        __syncthreads();
        for (int i = t; i < BATCH; i += 256) {
            const int a = which[i];
            g_bucket[atomicAdd(&run[a], 1)] = i;
        }
        return;
    }
    /* convert: 16 rows per block (8 warps x 2 rows, half-warp per row) */
    const int warp = t >> 5, lane = t & 31;
    const int row = (blockIdx.x - 1) * 16 + warp * 2 + (lane >> 4);
    if (row >= BATCH) return;
    const int p = lane & 15;                 /* k-pair within chunk */
    const float2* xr = (const float2*)(x + (size_t)row * INF) + p;
    const int q = p >> 2, w = p & 3;
    #pragma unroll
    for (int c = 0; c < NCH; c++) {
        const float2 v = xr[c * 16];
        uint32_t h, l;
        split2(v.x, v.y, h, l);
        uint32_t* dst = g_xs[c][row];
        dst[q * 8 + w]     = h;
        dst[q * 8 + 4 + w] = l;
    }
}

/* ---------------- kernel 2: split-bf16 mma.sync GEMM ----------------
   EXACT R10 per-chunk schedule; grid.z = 4 encodes (n-half, k-half).
   Each block covers 8 k-chunks; results combined via atomicAdd into a
   zeroed output. Bias contributed by k-half 0 only.
*/
__global__ __launch_bounds__(128, 3) void agent_mma_kernel(
    const float* __restrict__ x, const float* __restrict__ w,
    const float* __restrict__ bias, float* __restrict__ out)
{
    extern __shared__ char sm[];
    const uint32_t sb = smem_u32(sm);
    const int a     = blockIdx.y;
    const int mbase = blockIdx.x * MT;
    const int khalf = blockIdx.z & 1;
    const int nz    = blockIdx.z >> 1;
    const int c0    = khalf * NCH2;
    const int off   = g_offsets[a];
    const int cnt   = g_offsets[a + 1] - off;

    const int t    = threadIdx.x;
    const int lane = t & 31;
    const int warp = t >> 5;
    const int qr   = lane >> 2;
    const int qc   = lane & 3;

    /* ldmatrix per-lane address bases */
    const int aRow = ((lane >> 3) & 1) * 8;
    const int aK16 = ((lane >> 4) & 1) * 16;
    const int bRow = ((lane >> 4) & 1) * 8;
    const int bK16 = ((lane >> 3) & 1) * 16;
    uint32_t awb[2], alb[2], bxb[2], blb[2];
    #pragma unroll
    for (int mi = 0; mi < 2; mi++) {
        const uint32_t ro = (uint32_t)(warp * 32 + mi * 16 + aRow + (lane & 7)) * WROW_B + aK16;
        awb[mi] = sb + ST_WHI + ro;
        alb[mi] = sb + ST_WLO + ro;
    }
    #pragma unroll
    for (int nb = 0; nb < 2; nb++) {
        const uint32_t ro = (uint32_t)(nb * 16 + bRow + (lane & 7)) * WROW_B + bK16;
        bxb[nb] = sb + ST_XHI + ro;
        blb[nb] = sb + ST_XLO + ro;
    }

    /* coalesced W load mapping: 4 rows per warp-pass, 8 passes per chunk */
    const int wlr = lane >> 3;
    const int wlc = lane & 7;
    const float* Wbase = w + (size_t)a * OUTF * INF
                       + (size_t)(mbase + warp * 32 + wlr) * INF + wlc * 4;
    const uint32_t wsrow = (uint32_t)(warp * 32 + wlr);

    /* X mapping: slot = t>>2 (0..31), q = t&3 */
    const int xslot = t >> 2, xq4 = t & 3;
    const uint32_t xdst = sb + (uint32_t)xslot * WROW_B + xq4 * 16;

    float4 wpre[8];

    for (int n0 = nz * NT; n0 < cnt; n0 += 2 * NT) {
        const int cntc = min(NT, cnt - n0);
        int sg = off + n0 + xslot;
        if (sg > BATCH - 1) sg = BATCH - 1;
        const int xrowg = g_bucket[sg];

        float acc[2][4][4];
        #pragma unroll
        for (int mi = 0; mi < 2; mi++)
            #pragma unroll
            for (int ni = 0; ni < 4; ni++)
                #pragma unroll
                for (int r = 0; r < 4; r++) acc[mi][ni][r] = 0.f;

        /* issue W LDG (to regs) + X cp.async (to stage c&1) for chunk c */
        auto ldg = [&](int c) {
            const int k0 = c * TK;
            #pragma unroll
            for (int ro = 0; ro < 8; ro++)
                wpre[ro] = *(const float4*)(Wbase + (size_t)ro * 4 * INF + k0);
            const uint32_t so = (uint32_t)(c & 1) * ST_SIZE;
            const uint32_t* xsrc = &g_xs[c][xrowg][xq4 * 8];
            CP_ASYNC16(xdst + ST_XHI + so, xsrc);
            CP_ASYNC16(xdst + ST_XLO + so, xsrc + 4);
        };

        auto sts = [&](int s) {
            char* dw = sm + (size_t)s * ST_SIZE + wsrow * WROW_B + wlc * 8;
            #pragma unroll
            for (int ro = 0; ro < 8; ro++) {
                uint32_t h0, l0, h1, l1;
                split2(wpre[ro].x, wpre[ro].y, h0, l0);
                split2(wpre[ro].z, wpre[ro].w, h1, l1);
                const uint32_t roff = (uint32_t)ro * 4 * WROW_B;
                *(uint2*)(dw + ST_WHI + roff) = make_uint2(h0, h1);
                *(uint2*)(dw + ST_WLO + roff) = make_uint2(l0, l1);
            }
        };

        auto compute = [&](int s) {
            const uint32_t so = (uint32_t)s * ST_SIZE;
            #pragma unroll
            for (int kk = 0; kk < 2; kk++) {
                const uint32_t ko = so + kk * 32;
                uint32_t ahi[2][4], alo[2][4];
                #pragma unroll
                for (int mi = 0; mi < 2; mi++) {
                    LDSM_X4(ahi[mi][0], ahi[mi][1], ahi[mi][2], ahi[mi][3], awb[mi] + ko);
                    LDSM_X4(alo[mi][0], alo[mi][1], alo[mi][2], alo[mi][3], alb[mi] + ko);
                }
                #pragma unroll
                for (int nb = 0; nb < 2; nb++) {
                    uint32_t bh4[4], bl4[4];
                    LDSM_X4(bh4[0], bh4[1], bh4[2], bh4[3], bxb[nb] + ko);
                    LDSM_X4(bl4[0], bl4[1], bl4[2], bl4[3], blb[nb] + ko);
                    #pragma unroll
                    for (int half = 0; half < 2; half++) {
                        const int ni = nb * 2 + half;
                        uint32_t bh[2] = {bh4[2 * half], bh4[2 * half + 1]};
                        uint32_t bl[2] = {bl4[2 * half], bl4[2 * half + 1]};
                        #pragma unroll
                        for (int mi = 0; mi < 2; mi++) {
                            mma_bf16(acc[mi][ni], ahi[mi], bh);
                            mma_bf16(acc[mi][ni], alo[mi], bh);
                            mma_bf16(acc[mi][ni], ahi[mi], bl);
                        }
                    }
                }
            }
        };

        ldg(c0);          /* W regs + X cp.async stage 0 (c0 even) */
        sts(0);           /* W stage 0 */
        for (int cc = 0; cc < NCH2; cc++) {
            const int c = c0 + cc;
            CP_WAIT_ALL();
            __syncthreads();
            if (cc + 1 < NCH2) ldg(c + 1);
            compute(c & 1);
            if (cc + 1 < NCH2) sts((c + 1) & 1);
        }

        /* epilogue: atomic accumulate into zeroed out; bias from khalf 0 */
        #pragma unroll
        for (int mi = 0; mi < 2; mi++) {
            const int mg = mbase + warp * 32 + mi * 16 + qr;
            const float b0 = khalf ? 0.f : bias[a * OUTF + mg];
            const float b8 = khalf ? 0.f : bias[a * OUTF + mg + 8];
            #pragma unroll
            for (int ni = 0; ni < 4; ni++) {
                const int n = ni * 8 + qc * 2;
                if (n < cntc) {
                    const int r = g_bucket[off + n0 + n];
                    atomicAdd(&out[(size_t)r * OUTF + mg],     acc[mi][ni][0] + b0);
                    atomicAdd(&out[(size_t)r * OUTF + mg + 8], acc[mi][ni][2] + b8);
                }
                if (n + 1 < cntc) {
                    const int r = g_bucket[off + n0 + n + 1];
                    atomicAdd(&out[(size_t)r * OUTF + mg],     acc[mi][ni][1] + b0);
                    atomicAdd(&out[(size_t)r * OUTF + mg + 8], acc[mi][ni][3] + b8);
                }
            }
        }
        __syncthreads();
    }
}

extern "C" void kernel_launch(void* const* d_in, const int* in_sizes, int n_in,
                              void* d_out, int out_size) {
    const int*   which = (const int*)d_in[0];
    const float* x     = (const float*)d_in[1];
    const float* w     = (const float*)d_in[2];
    const float* b     = (const float*)d_in[3];
    float* out = (float*)d_out;

    cudaFuncSetAttribute(agent_mma_kernel,
                         cudaFuncAttributeMaxDynamicSharedMemorySize, SM_TOT);

    cudaMemsetAsync(out, 0, (size_t)out_size * sizeof(float));
    prep_kernel<<<1 + (BATCH + 15) / 16, 256>>>(which, x);
    agent_mma_kernel<<<dim3(OUTF / MT, NAG, 4), 128, SM_TOT>>>(x, w, b, out);
}